// round 1
// baseline (speedup 1.0000x reference)
#include <cuda_runtime.h>
#include <cuda_bf16.h>
#include <math.h>

// ---------------- problem constants ----------------
#define BB 2
#define NN 2048
#define DD 2048
#define HH 16
#define QLORA 1536
#define KVLORA 512
#define DNOPE 128
#define DROPE 64
#define DVAL 128
#define QKD 192            // DNOPE + DROPE
#define MROWS (BB*NN)      // 4096
#define EPS 1e-6f
#define ATTN_SCALE 0.072168783648703220563f  // 192^-0.5

// ---------------- scratch (device globals; no cudaMalloc allowed) ----------
__device__ float g_qa  [(size_t)MROWS*QLORA];          // x@wq_a, rmsnormed in place
__device__ float g_q   [(size_t)MROWS*HH*QKD];         // qa@wq_b (pre-rope)
__device__ float g_qT  [(size_t)BB*HH*NN*QKD];         // [b,h,n,192] roped
__device__ float g_kva [(size_t)MROWS*(DROPE+KVLORA)];
__device__ float g_kvcn[(size_t)MROWS*KVLORA];
__device__ float g_krope[(size_t)MROWS*DROPE];         // roped k_rope
__device__ float g_kv  [(size_t)MROWS*HH*(DNOPE+DVAL)];
__device__ float g_kT  [(size_t)BB*HH*NN*QKD];         // [b,h,n,192]
__device__ float g_vT  [(size_t)BB*HH*NN*DVAL];        // [b,h,n,128]
__device__ float g_ao  [(size_t)MROWS*HH*DVAL];        // [b,n,h*128] attn out

// ---------------- block sum reduce ----------------
__device__ __forceinline__ float block_reduce_sum(float v) {
    __shared__ float red[32];
    int lane = threadIdx.x & 31, w = threadIdx.x >> 5;
    #pragma unroll
    for (int o = 16; o; o >>= 1) v += __shfl_xor_sync(0xffffffffu, v, o);
    if (lane == 0) red[w] = v;
    __syncthreads();
    int nw = blockDim.x >> 5;
    float r = (threadIdx.x < nw) ? red[threadIdx.x] : 0.f;
    if (w == 0) {
        #pragma unroll
        for (int o = 16; o; o >>= 1) r += __shfl_xor_sync(0xffffffffu, r, o);
        if (lane == 0) red[0] = r;
    }
    __syncthreads();
    float out = red[0];
    __syncthreads();
    return out;
}

// ---------------- generic fp32 SGEMM: C[M,N] = A[M,K] @ B[K,N] --------------
// 64x64 tile, BK=16, 256 threads (16x16), 4x4 per thread, float4 everywhere.
// Requires M%64==0, N%64==0, K%16==0 (true for all 5 GEMMs here).
__global__ __launch_bounds__(256) void sgemm64(
    const float* __restrict__ A, const float* __restrict__ B,
    float* __restrict__ C, int M, int N, int K) {
    __shared__ float As[16][64];
    __shared__ float Bs[16][68];   // 68-pad: float4-aligned rows, fewer conflicts
    int tx = threadIdx.x, ty = threadIdx.y;
    int tid = ty * 16 + tx;
    int row0 = blockIdx.y * 64;
    int col0 = blockIdx.x * 64;

    int ar = tid >> 2;            // 0..63 A row in tile
    int ak = (tid & 3) * 4;       // k offset within BK
    int br = tid >> 4;            // 0..15 B k-row
    int bc = (tid & 15) * 4;      // 0..60 B col in tile

    float acc[4][4] = {};
    for (int k0 = 0; k0 < K; k0 += 16) {
        float4 av = *reinterpret_cast<const float4*>(A + (size_t)(row0 + ar) * K + k0 + ak);
        float4 bv = *reinterpret_cast<const float4*>(B + (size_t)(k0 + br) * N + col0 + bc);
        As[ak + 0][ar] = av.x; As[ak + 1][ar] = av.y;
        As[ak + 2][ar] = av.z; As[ak + 3][ar] = av.w;
        *reinterpret_cast<float4*>(&Bs[br][bc]) = bv;
        __syncthreads();
        #pragma unroll
        for (int k = 0; k < 16; k++) {
            float4 a = *reinterpret_cast<const float4*>(&As[k][ty * 4]);
            float4 b = *reinterpret_cast<const float4*>(&Bs[k][tx * 4]);
            float aa[4] = {a.x, a.y, a.z, a.w};
            float bb[4] = {b.x, b.y, b.z, b.w};
            #pragma unroll
            for (int i = 0; i < 4; i++)
                #pragma unroll
                for (int j = 0; j < 4; j++)
                    acc[i][j] = fmaf(aa[i], bb[j], acc[i][j]);
        }
        __syncthreads();
    }
    #pragma unroll
    for (int i = 0; i < 4; i++) {
        float4 v = make_float4(acc[i][0], acc[i][1], acc[i][2], acc[i][3]);
        *reinterpret_cast<float4*>(C + (size_t)(row0 + ty * 4 + i) * N + col0 + tx * 4) = v;
    }
}

// ---------------- rmsnorm over rows (in/out may alias per-row) --------------
__global__ __launch_bounds__(256) void rmsnorm_kernel(
    const float* __restrict__ in, const float* __restrict__ w,
    float* __restrict__ out, int W) {
    size_t row = blockIdx.x;
    const float* r = in + row * W;
    float ss = 0.f;
    for (int i = threadIdx.x; i < W; i += 256) { float v = r[i]; ss += v * v; }
    ss = block_reduce_sum(ss);
    float sc = rsqrtf(ss / (float)W + EPS);
    for (int i = threadIdx.x; i < W; i += 256)
        out[row * W + i] = r[i] * sc * w[i];
}

// ---------------- q rope + transpose to [b,h,n,192] ------------------------
__global__ __launch_bounds__(192) void qrope_kernel(
    const float* __restrict__ q, const float* __restrict__ cosv,
    const float* __restrict__ sinv, float* __restrict__ qT) {
    int n = blockIdx.x, h = blockIdx.y, b = blockIdx.z;
    int d = threadIdx.x;
    const float* src = q + ((size_t)(b * NN + n) * HH + h) * QKD;
    float v;
    if (d < DNOPE) {
        v = src[d];
    } else {
        int r = d - DNOPE;
        int i = r >> 1;
        float x0 = src[DNOPE + 2 * i], x1 = src[DNOPE + 2 * i + 1];
        float c = cosv[n * (DROPE / 2) + i], s = sinv[n * (DROPE / 2) + i];
        v = (r & 1) ? fmaf(x0, s, x1 * c) : fmaf(x0, c, -x1 * s);
    }
    qT[(((size_t)b * HH + h) * NN + n) * QKD + d] = v;
}

// ---------------- kv_a: rope(k_rope) + rmsnorm(kv_c) ------------------------
__global__ __launch_bounds__(256) void kva_kernel(
    const float* __restrict__ kva, const float* __restrict__ kvw,
    const float* __restrict__ cosv, const float* __restrict__ sinv,
    float* __restrict__ krope, float* __restrict__ kvcn) {
    size_t row = blockIdx.x;
    int n = (int)(row % NN);
    const float* src = kva + row * (DROPE + KVLORA);
    float ss = 0.f;
    for (int i = threadIdx.x; i < KVLORA; i += 256) {
        float v = src[DROPE + i]; ss += v * v;
    }
    ss = block_reduce_sum(ss);
    float sc = rsqrtf(ss / (float)KVLORA + EPS);
    for (int i = threadIdx.x; i < KVLORA; i += 256)
        kvcn[row * KVLORA + i] = src[DROPE + i] * sc * kvw[i];
    if (threadIdx.x < DROPE) {
        int t = threadIdx.x;
        int i = t >> 1;
        float x0 = src[2 * i], x1 = src[2 * i + 1];
        float c = cosv[n * (DROPE / 2) + i], s = sinv[n * (DROPE / 2) + i];
        krope[row * DROPE + t] = (t & 1) ? fmaf(x0, s, x1 * c) : fmaf(x0, c, -x1 * s);
    }
}

// ---------------- build K [b,h,n,192] and V [b,h,n,128] ---------------------
__global__ __launch_bounds__(192) void buildkv_kernel(
    const float* __restrict__ kv, const float* __restrict__ krope,
    float* __restrict__ kT, float* __restrict__ vT) {
    int n = blockIdx.x, h = blockIdx.y, b = blockIdx.z;
    int d = threadIdx.x;
    size_t row = (size_t)b * NN + n;
    const float* src = kv + (row * HH + h) * (DNOPE + DVAL);
    size_t o = ((size_t)b * HH + h) * NN + n;
    if (d < DNOPE) {
        kT[o * QKD + d] = src[d];
        vT[o * DVAL + d] = src[DNOPE + d];
    } else {
        kT[o * QKD + d] = krope[row * DROPE + (d - DNOPE)];
    }
}

// ---------------- flash attention (causal), BQ=BK=64, fp32 ------------------
// smem: Qs[64][193] + Ks[64][193] + Vs[64][128] + Ps[64][64] = 147,968 B
#define QPITCH 193
#define SMEM_ATTN ((64*QPITCH*2 + 64*128 + 64*64) * 4)
__global__ __launch_bounds__(256) void attn_kernel(
    const float* __restrict__ qT, const float* __restrict__ kT,
    const float* __restrict__ vT, float* __restrict__ ao) {
    extern __shared__ float sm[];
    float* Qs = sm;                       // [64][193]
    float* Ks = Qs + 64 * QPITCH;         // [64][193]
    float* Vs = Ks + 64 * QPITCH;         // [64][128]
    float* Ps = Vs + 64 * 128;            // [64][64]

    int tid = threadIdx.x;
    int tx = tid & 15, ty = tid >> 4;
    int qt = blockIdx.x, h = blockIdx.y, b = blockIdx.z;
    int q0 = qt * 64;
    size_t bh = ((size_t)b * HH + h) * NN;

    // Load Q tile once (float4 global reads, scalar padded smem stores)
    const float* Qg = qT + (bh + q0) * QKD;
    for (int i = tid; i < 64 * 48; i += 256) {
        int r = i / 48, c4 = (i % 48) * 4;
        float4 v = *reinterpret_cast<const float4*>(Qg + (size_t)r * QKD + c4);
        Qs[r * QPITCH + c4 + 0] = v.x; Qs[r * QPITCH + c4 + 1] = v.y;
        Qs[r * QPITCH + c4 + 2] = v.z; Qs[r * QPITCH + c4 + 3] = v.w;
    }

    float o[4][8] = {};
    float m_[4], l_[4];
    #pragma unroll
    for (int i = 0; i < 4; i++) { m_[i] = -1e30f; l_[i] = 0.f; }

    for (int kt = 0; kt <= qt; kt++) {
        __syncthreads();  // guard Ks/Vs/Ps against previous iteration readers
        const float* Kg = kT + (bh + (size_t)kt * 64) * QKD;
        const float* Vg = vT + (bh + (size_t)kt * 64) * DVAL;
        for (int i = tid; i < 64 * 48; i += 256) {
            int r = i / 48, c4 = (i % 48) * 4;
            float4 v = *reinterpret_cast<const float4*>(Kg + (size_t)r * QKD + c4);
            Ks[r * QPITCH + c4 + 0] = v.x; Ks[r * QPITCH + c4 + 1] = v.y;
            Ks[r * QPITCH + c4 + 2] = v.z; Ks[r * QPITCH + c4 + 3] = v.w;
        }
        {
            const float4* Vg4 = reinterpret_cast<const float4*>(Vg);
            float4* Vs4 = reinterpret_cast<float4*>(Vs);
            for (int i = tid; i < 64 * 128 / 4; i += 256) Vs4[i] = Vg4[i];
        }
        __syncthreads();

        // ---- S = Q K^T (64x64 tile, 4x4 per thread over 192 dims) ----
        float s_[4][4] = {};
        #pragma unroll 4
        for (int d = 0; d < QKD; d++) {
            float qf[4], kf[4];
            #pragma unroll
            for (int i = 0; i < 4; i++) qf[i] = Qs[(ty * 4 + i) * QPITCH + d];
            #pragma unroll
            for (int j = 0; j < 4; j++) kf[j] = Ks[(tx * 4 + j) * QPITCH + d];
            #pragma unroll
            for (int i = 0; i < 4; i++)
                #pragma unroll
                for (int j = 0; j < 4; j++)
                    s_[i][j] = fmaf(qf[i], kf[j], s_[i][j]);
        }

        bool diag = (kt == qt);
        #pragma unroll
        for (int i = 0; i < 4; i++)
            #pragma unroll
            for (int j = 0; j < 4; j++) {
                s_[i][j] *= ATTN_SCALE;
                if (diag && (tx * 4 + j) > (ty * 4 + i)) s_[i][j] = -1e30f;
            }

        // ---- online softmax (row groups = 16 lanes sharing ty) ----
        #pragma unroll
        for (int i = 0; i < 4; i++) {
            float mx = fmaxf(fmaxf(s_[i][0], s_[i][1]), fmaxf(s_[i][2], s_[i][3]));
            #pragma unroll
            for (int off = 8; off >= 1; off >>= 1)
                mx = fmaxf(mx, __shfl_xor_sync(0xffffffffu, mx, off));
            float mn = fmaxf(m_[i], mx);
            float al = __expf(m_[i] - mn);
            float ps = 0.f;
            #pragma unroll
            for (int j = 0; j < 4; j++) {
                float p = __expf(s_[i][j] - mn);
                s_[i][j] = p;
                ps += p;
            }
            #pragma unroll
            for (int off = 8; off >= 1; off >>= 1)
                ps += __shfl_xor_sync(0xffffffffu, ps, off);
            l_[i] = l_[i] * al + ps;
            m_[i] = mn;
            #pragma unroll
            for (int j = 0; j < 8; j++) o[i][j] *= al;
        }

        // stage P to smem for the PV phase
        #pragma unroll
        for (int i = 0; i < 4; i++)
            #pragma unroll
            for (int j = 0; j < 4; j++)
                Ps[(ty * 4 + i) * 64 + tx * 4 + j] = s_[i][j];
        __syncthreads();

        // ---- O += P V (each thread: 4 rows x 8 V-cols) ----
        #pragma unroll 4
        for (int k = 0; k < 64; k++) {
            float pf[4];
            #pragma unroll
            for (int i = 0; i < 4; i++) pf[i] = Ps[(ty * 4 + i) * 64 + k];
            float4 v0 = *reinterpret_cast<const float4*>(&Vs[k * 128 + tx * 8]);
            float4 v1 = *reinterpret_cast<const float4*>(&Vs[k * 128 + tx * 8 + 4]);
            float vf[8] = {v0.x, v0.y, v0.z, v0.w, v1.x, v1.y, v1.z, v1.w};
            #pragma unroll
            for (int i = 0; i < 4; i++)
                #pragma unroll
                for (int j = 0; j < 8; j++)
                    o[i][j] = fmaf(pf[i], vf[j], o[i][j]);
        }
    }

    // epilogue: normalize + write [b, n, h*128]
    #pragma unroll
    for (int i = 0; i < 4; i++) {
        float inv = 1.f / l_[i];
        size_t base = ((size_t)(b * NN + q0 + ty * 4 + i)) * (HH * DVAL) + h * DVAL + tx * 8;
        float4 w0 = make_float4(o[i][0] * inv, o[i][1] * inv, o[i][2] * inv, o[i][3] * inv);
        float4 w1 = make_float4(o[i][4] * inv, o[i][5] * inv, o[i][6] * inv, o[i][7] * inv);
        *reinterpret_cast<float4*>(ao + base) = w0;
        *reinterpret_cast<float4*>(ao + base + 4) = w1;
    }
}

// ---------------- launch -----------------------------------------------------
static void launch_sgemm(const float* A, const float* B, float* C, int M, int N, int K) {
    dim3 grid(N / 64, M / 64), block(16, 16);
    sgemm64<<<grid, block>>>(A, B, C, M, N, K);
}

extern "C" void kernel_launch(void* const* d_in, const int* in_sizes, int n_in,
                              void* d_out, int out_size) {
    const float* x        = (const float*)d_in[0];
    // d_in[1] = start_pos (int32, == 0 here; positions are sequence indices)
    const float* rope_cos = (const float*)d_in[2];
    const float* rope_sin = (const float*)d_in[3];
    const float* wq_a     = (const float*)d_in[4];
    const float* q_norm_w = (const float*)d_in[5];
    const float* wq_b     = (const float*)d_in[6];
    const float* wkv_a    = (const float*)d_in[7];
    const float* kv_norm_w= (const float*)d_in[8];
    const float* wkv_b    = (const float*)d_in[9];
    const float* w_out    = (const float*)d_in[10];
    float* out = (float*)d_out;

    float *qa, *q, *qTp, *kva, *kvcn, *krope, *kv, *kTp, *vTp, *aop;
    cudaGetSymbolAddress((void**)&qa,   g_qa);
    cudaGetSymbolAddress((void**)&q,    g_q);
    cudaGetSymbolAddress((void**)&qTp,  g_qT);
    cudaGetSymbolAddress((void**)&kva,  g_kva);
    cudaGetSymbolAddress((void**)&kvcn, g_kvcn);
    cudaGetSymbolAddress((void**)&krope,g_krope);
    cudaGetSymbolAddress((void**)&kv,   g_kv);
    cudaGetSymbolAddress((void**)&kTp,  g_kT);
    cudaGetSymbolAddress((void**)&vTp,  g_vT);
    cudaGetSymbolAddress((void**)&aop,  g_ao);

    cudaFuncSetAttribute(attn_kernel, cudaFuncAttributeMaxDynamicSharedMemorySize, SMEM_ATTN);

    // Q path
    launch_sgemm(x, wq_a, qa, MROWS, QLORA, DD);
    rmsnorm_kernel<<<MROWS, 256>>>(qa, q_norm_w, qa, QLORA);
    launch_sgemm(qa, wq_b, q, MROWS, HH * QKD, QLORA);
    {
        dim3 g(NN, HH, BB);
        qrope_kernel<<<g, 192>>>(q, rope_cos, rope_sin, qTp);
    }

    // KV path
    launch_sgemm(x, wkv_a, kva, MROWS, DROPE + KVLORA, DD);
    kva_kernel<<<MROWS, 256>>>(kva, kv_norm_w, rope_cos, rope_sin, krope, kvcn);
    launch_sgemm(kvcn, wkv_b, kv, MROWS, HH * (DNOPE + DVAL), KVLORA);
    {
        dim3 g(NN, HH, BB);
        buildkv_kernel<<<g, 192>>>(kv, krope, kTp, vTp);
    }

    // attention
    {
        dim3 g(NN / 64, HH, BB);
        attn_kernel<<<g, 256, SMEM_ATTN>>>(qTp, kTp, vTp, aop);
    }

    // output projection
    launch_sgemm(aop, w_out, out, MROWS, DD, HH * DVAL);
}

// round 3
// speedup vs baseline: 1.7292x; 1.7292x over previous
#include <cuda_runtime.h>
#include <cuda_bf16.h>
#include <cstdint>
#include <math.h>

// ---------------- problem constants ----------------
#define BB 2
#define NN 2048
#define DD 2048
#define HH 16
#define QLORA 1536
#define KVLORA 512
#define DNOPE 128
#define DROPE 64
#define DVAL 128
#define QKD 192            // DNOPE + DROPE
#define MROWS (BB*NN)      // 4096
#define EPS 1e-6f
#define ATTN_SCALE 0.072168783648703220563f  // 192^-0.5

// ---------------- scratch (device globals; no cudaMalloc allowed) ----------
__device__ float g_qa  [(size_t)MROWS*QLORA];
__device__ float g_q   [(size_t)MROWS*HH*QKD];
__device__ float g_qT  [(size_t)BB*HH*NN*QKD];
__device__ float g_kva [(size_t)MROWS*(DROPE+KVLORA)];
__device__ float g_kvcn[(size_t)MROWS*KVLORA];
__device__ float g_krope[(size_t)MROWS*DROPE];
__device__ float g_kv  [(size_t)MROWS*HH*(DNOPE+DVAL)];
__device__ float g_kT  [(size_t)BB*HH*NN*QKD];
__device__ float g_vT  [(size_t)BB*HH*NN*DVAL];
__device__ float g_ao  [(size_t)MROWS*HH*DVAL];

// ---------------- helpers ----------------
__device__ __forceinline__ uint32_t f2tf32(float x) {
    uint32_t r;
    asm("cvt.rna.tf32.f32 %0, %1;" : "=r"(r) : "f"(x));
    return r;
}

__device__ __forceinline__ void mma_tf32(float* c, const uint32_t* a, const uint32_t* b) {
    asm volatile(
        "mma.sync.aligned.m16n8k8.row.col.f32.tf32.tf32.f32 "
        "{%0,%1,%2,%3}, {%4,%5,%6,%7}, {%8,%9}, {%0,%1,%2,%3};"
        : "+f"(c[0]), "+f"(c[1]), "+f"(c[2]), "+f"(c[3])
        : "r"(a[0]), "r"(a[1]), "r"(a[2]), "r"(a[3]), "r"(b[0]), "r"(b[1]));
}

__device__ __forceinline__ float block_reduce_sum(float v) {
    __shared__ float red[32];
    int lane = threadIdx.x & 31, w = threadIdx.x >> 5;
    #pragma unroll
    for (int o = 16; o; o >>= 1) v += __shfl_xor_sync(0xffffffffu, v, o);
    if (lane == 0) red[w] = v;
    __syncthreads();
    int nw = blockDim.x >> 5;
    float r = (threadIdx.x < nw) ? red[threadIdx.x] : 0.f;
    if (w == 0) {
        #pragma unroll
        for (int o = 16; o; o >>= 1) r += __shfl_xor_sync(0xffffffffu, r, o);
        if (lane == 0) red[0] = r;
    }
    __syncthreads();
    float out = red[0];
    __syncthreads();
    return out;
}

// ---------------- tf32 tensor-core GEMM: C[M,N] = A[M,K] @ B[K,N] ----------
// Tile 128 x BN, BK=16, 256 threads (8 warps, 4x2). Each warp: 32 x (BN/2),
// built from m16n8k8 fragments. A in smem k-major pitch 136, B row-major
// pitch BN+8 -> fragment reads are bank-conflict-free (8*tg + g distinct).
// Requires M%128==0, N%BN==0, K%16==0.
template <int BN>
__global__ __launch_bounds__(256) void gemm_tf32(
    const float* __restrict__ A, const float* __restrict__ B,
    float* __restrict__ C, int M, int N, int K) {
    constexpr int NFRAG = BN / 16;          // n-fragments per warp
    constexpr int BPITCH = BN + 8;
    __shared__ uint32_t As[2][16][136];     // [k][m]
    __shared__ uint32_t Bs[2][16][BPITCH];  // [k][n]

    const int tid = threadIdx.x;
    const int wid = tid >> 5, lane = tid & 31;
    const int g = lane >> 2, tg = lane & 3;
    const int wm = (wid & 3) * 32;
    const int wn = (wid >> 2) * (BN / 2);
    const int row0 = blockIdx.y * 128;
    const int col0 = blockIdx.x * BN;

    // global->smem mapping
    const int ar  = tid >> 2;           // 0..63 (A row in tile; second row ar+64)
    const int akc = (tid & 3) * 4;      // k offset
    const float* Ag0 = A + (size_t)(row0 + ar) * K + akc;
    const float* Ag1 = Ag0 + (size_t)64 * K;

    int brow, bcol;
    if (BN == 128) { brow = tid >> 5; bcol = (tid & 31) * 4; }
    else           { brow = tid >> 4; bcol = (tid & 15) * 4; }
    const float* Bg0 = B + (size_t)brow * N + col0 + bcol;
    const float* Bg1 = Bg0 + (size_t)8 * N;   // used only for BN==128

    float acc[2][NFRAG][4];
    #pragma unroll
    for (int i = 0; i < 2; i++)
        #pragma unroll
        for (int j = 0; j < NFRAG; j++)
            #pragma unroll
            for (int k = 0; k < 4; k++) acc[i][j][k] = 0.f;

    const int ntiles = K / 16;

    // ---- prologue: tile 0 ----
    {
        float4 va0 = *reinterpret_cast<const float4*>(Ag0);
        float4 va1 = *reinterpret_cast<const float4*>(Ag1);
        As[0][akc + 0][ar] = f2tf32(va0.x); As[0][akc + 1][ar] = f2tf32(va0.y);
        As[0][akc + 2][ar] = f2tf32(va0.z); As[0][akc + 3][ar] = f2tf32(va0.w);
        As[0][akc + 0][ar + 64] = f2tf32(va1.x); As[0][akc + 1][ar + 64] = f2tf32(va1.y);
        As[0][akc + 2][ar + 64] = f2tf32(va1.z); As[0][akc + 3][ar + 64] = f2tf32(va1.w);
        float4 vb0 = *reinterpret_cast<const float4*>(Bg0);
        uint4 u0 = make_uint4(f2tf32(vb0.x), f2tf32(vb0.y), f2tf32(vb0.z), f2tf32(vb0.w));
        *reinterpret_cast<uint4*>(&Bs[0][brow][bcol]) = u0;
        if (BN == 128) {
            float4 vb1 = *reinterpret_cast<const float4*>(Bg1);
            uint4 u1 = make_uint4(f2tf32(vb1.x), f2tf32(vb1.y), f2tf32(vb1.z), f2tf32(vb1.w));
            *reinterpret_cast<uint4*>(&Bs[0][brow + 8][bcol]) = u1;
        }
    }
    __syncthreads();

    for (int t = 0; t < ntiles; t++) {
        const int cur = t & 1;
        float4 na0, na1, nb0, nb1;
        const bool more = (t + 1 < ntiles);
        if (more) {
            na0 = *reinterpret_cast<const float4*>(Ag0 + (t + 1) * 16);
            na1 = *reinterpret_cast<const float4*>(Ag1 + (t + 1) * 16);
            nb0 = *reinterpret_cast<const float4*>(Bg0 + (size_t)(t + 1) * 16 * N);
            if (BN == 128)
                nb1 = *reinterpret_cast<const float4*>(Bg1 + (size_t)(t + 1) * 16 * N);
        }

        // ---- compute on buffer `cur` (2 k-steps of 8) ----
        #pragma unroll
        for (int s = 0; s < 2; s++) {
            uint32_t af[2][4];
            #pragma unroll
            for (int mf = 0; mf < 2; mf++) {
                int m = wm + mf * 16 + g;
                af[mf][0] = As[cur][s * 8 + tg    ][m];
                af[mf][1] = As[cur][s * 8 + tg    ][m + 8];
                af[mf][2] = As[cur][s * 8 + tg + 4][m];
                af[mf][3] = As[cur][s * 8 + tg + 4][m + 8];
            }
            uint32_t bf[NFRAG][2];
            #pragma unroll
            for (int j = 0; j < NFRAG; j++) {
                int n = wn + j * 8 + g;
                bf[j][0] = Bs[cur][s * 8 + tg    ][n];
                bf[j][1] = Bs[cur][s * 8 + tg + 4][n];
            }
            #pragma unroll
            for (int mf = 0; mf < 2; mf++)
                #pragma unroll
                for (int j = 0; j < NFRAG; j++)
                    mma_tf32(acc[mf][j], af[mf], bf[j]);
        }

        if (more) {
            const int nxt = cur ^ 1;
            As[nxt][akc + 0][ar] = f2tf32(na0.x); As[nxt][akc + 1][ar] = f2tf32(na0.y);
            As[nxt][akc + 2][ar] = f2tf32(na0.z); As[nxt][akc + 3][ar] = f2tf32(na0.w);
            As[nxt][akc + 0][ar + 64] = f2tf32(na1.x); As[nxt][akc + 1][ar + 64] = f2tf32(na1.y);
            As[nxt][akc + 2][ar + 64] = f2tf32(na1.z); As[nxt][akc + 3][ar + 64] = f2tf32(na1.w);
            uint4 u0 = make_uint4(f2tf32(nb0.x), f2tf32(nb0.y), f2tf32(nb0.z), f2tf32(nb0.w));
            *reinterpret_cast<uint4*>(&Bs[nxt][brow][bcol]) = u0;
            if (BN == 128) {
                uint4 u1 = make_uint4(f2tf32(nb1.x), f2tf32(nb1.y), f2tf32(nb1.z), f2tf32(nb1.w));
                *reinterpret_cast<uint4*>(&Bs[nxt][brow + 8][bcol]) = u1;
            }
            __syncthreads();
        }
    }

    // ---- epilogue ----
    #pragma unroll
    for (int mf = 0; mf < 2; mf++) {
        #pragma unroll
        for (int j = 0; j < NFRAG; j++) {
            int r = row0 + wm + mf * 16 + g;
            int c = col0 + wn + j * 8 + tg * 2;
            *reinterpret_cast<float2*>(C + (size_t)r * N + c) =
                make_float2(acc[mf][j][0], acc[mf][j][1]);
            *reinterpret_cast<float2*>(C + (size_t)(r + 8) * N + c) =
                make_float2(acc[mf][j][2], acc[mf][j][3]);
        }
    }
}

// ---------------- rmsnorm over rows ----------------
__global__ __launch_bounds__(256) void rmsnorm_kernel(
    const float* __restrict__ in, const float* __restrict__ w,
    float* __restrict__ out, int W) {
    size_t row = blockIdx.x;
    const float* r = in + row * W;
    float ss = 0.f;
    for (int i = threadIdx.x; i < W; i += 256) { float v = r[i]; ss += v * v; }
    ss = block_reduce_sum(ss);
    float sc = rsqrtf(ss / (float)W + EPS);
    for (int i = threadIdx.x; i < W; i += 256)
        out[row * W + i] = r[i] * sc * w[i];
}

// ---------------- q rope + transpose to [b,h,n,192] ------------------------
__global__ __launch_bounds__(192) void qrope_kernel(
    const float* __restrict__ q, const float* __restrict__ cosv,
    const float* __restrict__ sinv, float* __restrict__ qT) {
    int n = blockIdx.x, h = blockIdx.y, b = blockIdx.z;
    int d = threadIdx.x;
    const float* src = q + ((size_t)(b * NN + n) * HH + h) * QKD;
    float v;
    if (d < DNOPE) {
        v = src[d];
    } else {
        int r = d - DNOPE;
        int i = r >> 1;
        float x0 = src[DNOPE + 2 * i], x1 = src[DNOPE + 2 * i + 1];
        float c = cosv[n * (DROPE / 2) + i], s = sinv[n * (DROPE / 2) + i];
        v = (r & 1) ? fmaf(x0, s, x1 * c) : fmaf(x0, c, -x1 * s);
    }
    qT[(((size_t)b * HH + h) * NN + n) * QKD + d] = v;
}

// ---------------- kv_a: rope(k_rope) + rmsnorm(kv_c) ------------------------
__global__ __launch_bounds__(256) void kva_kernel(
    const float* __restrict__ kva, const float* __restrict__ kvw,
    const float* __restrict__ cosv, const float* __restrict__ sinv,
    float* __restrict__ krope, float* __restrict__ kvcn) {
    size_t row = blockIdx.x;
    int n = (int)(row % NN);
    const float* src = kva + row * (DROPE + KVLORA);
    float ss = 0.f;
    for (int i = threadIdx.x; i < KVLORA; i += 256) {
        float v = src[DROPE + i]; ss += v * v;
    }
    ss = block_reduce_sum(ss);
    float sc = rsqrtf(ss / (float)KVLORA + EPS);
    for (int i = threadIdx.x; i < KVLORA; i += 256)
        kvcn[row * KVLORA + i] = src[DROPE + i] * sc * kvw[i];
    if (threadIdx.x < DROPE) {
        int t = threadIdx.x;
        int i = t >> 1;
        float x0 = src[2 * i], x1 = src[2 * i + 1];
        float c = cosv[n * (DROPE / 2) + i], s = sinv[n * (DROPE / 2) + i];
        krope[row * DROPE + t] = (t & 1) ? fmaf(x0, s, x1 * c) : fmaf(x0, c, -x1 * s);
    }
}

// ---------------- build K [b,h,n,192] and V [b,h,n,128] ---------------------
__global__ __launch_bounds__(192) void buildkv_kernel(
    const float* __restrict__ kv, const float* __restrict__ krope,
    float* __restrict__ kT, float* __restrict__ vT) {
    int n = blockIdx.x, h = blockIdx.y, b = blockIdx.z;
    int d = threadIdx.x;
    size_t row = (size_t)b * NN + n;
    const float* src = kv + (row * HH + h) * (DNOPE + DVAL);
    size_t o = ((size_t)b * HH + h) * NN + n;
    if (d < DNOPE) {
        kT[o * QKD + d] = src[d];
        vT[o * DVAL + d] = src[DNOPE + d];
    } else {
        kT[o * QKD + d] = krope[row * DROPE + (d - DNOPE)];
    }
}

// ---------------- flash attention (causal), BQ=BK=64, fp32 ------------------
#define QPITCH 193
#define SMEM_ATTN ((64*QPITCH*2 + 64*128 + 64*64) * 4)
__global__ __launch_bounds__(256) void attn_kernel(
    const float* __restrict__ qT, const float* __restrict__ kT,
    const float* __restrict__ vT, float* __restrict__ ao) {
    extern __shared__ float sm[];
    float* Qs = sm;
    float* Ks = Qs + 64 * QPITCH;
    float* Vs = Ks + 64 * QPITCH;
    float* Ps = Vs + 64 * 128;

    int tid = threadIdx.x;
    int tx = tid & 15, ty = tid >> 4;
    int qt = blockIdx.x, h = blockIdx.y, b = blockIdx.z;
    int q0 = qt * 64;
    size_t bh = ((size_t)b * HH + h) * NN;

    const float* Qg = qT + (bh + q0) * QKD;
    for (int i = tid; i < 64 * 48; i += 256) {
        int r = i / 48, c4 = (i % 48) * 4;
        float4 v = *reinterpret_cast<const float4*>(Qg + (size_t)r * QKD + c4);
        Qs[r * QPITCH + c4 + 0] = v.x; Qs[r * QPITCH + c4 + 1] = v.y;
        Qs[r * QPITCH + c4 + 2] = v.z; Qs[r * QPITCH + c4 + 3] = v.w;
    }

    float o[4][8] = {};
    float m_[4], l_[4];
    #pragma unroll
    for (int i = 0; i < 4; i++) { m_[i] = -1e30f; l_[i] = 0.f; }

    for (int kt = 0; kt <= qt; kt++) {
        __syncthreads();
        const float* Kg = kT + (bh + (size_t)kt * 64) * QKD;
        const float* Vg = vT + (bh + (size_t)kt * 64) * DVAL;
        for (int i = tid; i < 64 * 48; i += 256) {
            int r = i / 48, c4 = (i % 48) * 4;
            float4 v = *reinterpret_cast<const float4*>(Kg + (size_t)r * QKD + c4);
            Ks[r * QPITCH + c4 + 0] = v.x; Ks[r * QPITCH + c4 + 1] = v.y;
            Ks[r * QPITCH + c4 + 2] = v.z; Ks[r * QPITCH + c4 + 3] = v.w;
        }
        {
            const float4* Vg4 = reinterpret_cast<const float4*>(Vg);
            float4* Vs4 = reinterpret_cast<float4*>(Vs);
            for (int i = tid; i < 64 * 128 / 4; i += 256) Vs4[i] = Vg4[i];
        }
        __syncthreads();

        float s_[4][4] = {};
        #pragma unroll 4
        for (int d = 0; d < QKD; d++) {
            float qf[4], kf[4];
            #pragma unroll
            for (int i = 0; i < 4; i++) qf[i] = Qs[(ty * 4 + i) * QPITCH + d];
            #pragma unroll
            for (int j = 0; j < 4; j++) kf[j] = Ks[(tx * 4 + j) * QPITCH + d];
            #pragma unroll
            for (int i = 0; i < 4; i++)
                #pragma unroll
                for (int j = 0; j < 4; j++)
                    s_[i][j] = fmaf(qf[i], kf[j], s_[i][j]);
        }

        bool diag = (kt == qt);
        #pragma unroll
        for (int i = 0; i < 4; i++)
            #pragma unroll
            for (int j = 0; j < 4; j++) {
                s_[i][j] *= ATTN_SCALE;
                if (diag && (tx * 4 + j) > (ty * 4 + i)) s_[i][j] = -1e30f;
            }

        #pragma unroll
        for (int i = 0; i < 4; i++) {
            float mx = fmaxf(fmaxf(s_[i][0], s_[i][1]), fmaxf(s_[i][2], s_[i][3]));
            #pragma unroll
            for (int off = 8; off >= 1; off >>= 1)
                mx = fmaxf(mx, __shfl_xor_sync(0xffffffffu, mx, off));
            float mn = fmaxf(m_[i], mx);
            float al = __expf(m_[i] - mn);
            float ps = 0.f;
            #pragma unroll
            for (int j = 0; j < 4; j++) {
                float p = __expf(s_[i][j] - mn);
                s_[i][j] = p;
                ps += p;
            }
            #pragma unroll
            for (int off = 8; off >= 1; off >>= 1)
                ps += __shfl_xor_sync(0xffffffffu, ps, off);
            l_[i] = l_[i] * al + ps;
            m_[i] = mn;
            #pragma unroll
            for (int j = 0; j < 8; j++) o[i][j] *= al;
        }

        #pragma unroll
        for (int i = 0; i < 4; i++)
            #pragma unroll
            for (int j = 0; j < 4; j++)
                Ps[(ty * 4 + i) * 64 + tx * 4 + j] = s_[i][j];
        __syncthreads();

        #pragma unroll 4
        for (int k = 0; k < 64; k++) {
            float pf[4];
            #pragma unroll
            for (int i = 0; i < 4; i++) pf[i] = Ps[(ty * 4 + i) * 64 + k];
            float4 v0 = *reinterpret_cast<const float4*>(&Vs[k * 128 + tx * 8]);
            float4 v1 = *reinterpret_cast<const float4*>(&Vs[k * 128 + tx * 8 + 4]);
            float vf[8] = {v0.x, v0.y, v0.z, v0.w, v1.x, v1.y, v1.z, v1.w};
            #pragma unroll
            for (int i = 0; i < 4; i++)
                #pragma unroll
                for (int j = 0; j < 8; j++)
                    o[i][j] = fmaf(pf[i], vf[j], o[i][j]);
        }
    }

    #pragma unroll
    for (int i = 0; i < 4; i++) {
        float inv = 1.f / l_[i];
        size_t base = ((size_t)(b * NN + q0 + ty * 4 + i)) * (HH * DVAL) + h * DVAL + tx * 8;
        float4 w0 = make_float4(o[i][0] * inv, o[i][1] * inv, o[i][2] * inv, o[i][3] * inv);
        float4 w1 = make_float4(o[i][4] * inv, o[i][5] * inv, o[i][6] * inv, o[i][7] * inv);
        *reinterpret_cast<float4*>(ao + base) = w0;
        *reinterpret_cast<float4*>(ao + base + 4) = w1;
    }
}

// ---------------- launch -----------------------------------------------------
static void launch_gemm(const float* A, const float* B, float* C, int M, int N, int K) {
    if (N % 128 == 0) {
        dim3 grid(N / 128, M / 128);
        gemm_tf32<128><<<grid, 256>>>(A, B, C, M, N, K);
    } else {
        dim3 grid(N / 64, M / 128);
        gemm_tf32<64><<<grid, 256>>>(A, B, C, M, N, K);
    }
}

extern "C" void kernel_launch(void* const* d_in, const int* in_sizes, int n_in,
                              void* d_out, int out_size) {
    const float* x        = (const float*)d_in[0];
    const float* rope_cos = (const float*)d_in[2];
    const float* rope_sin = (const float*)d_in[3];
    const float* wq_a     = (const float*)d_in[4];
    const float* q_norm_w = (const float*)d_in[5];
    const float* wq_b     = (const float*)d_in[6];
    const float* wkv_a    = (const float*)d_in[7];
    const float* kv_norm_w= (const float*)d_in[8];
    const float* wkv_b    = (const float*)d_in[9];
    const float* w_out    = (const float*)d_in[10];
    float* out = (float*)d_out;

    float *qa, *q, *qTp, *kva, *kvcn, *krope, *kv, *kTp, *vTp, *aop;
    cudaGetSymbolAddress((void**)&qa,   g_qa);
    cudaGetSymbolAddress((void**)&q,    g_q);
    cudaGetSymbolAddress((void**)&qTp,  g_qT);
    cudaGetSymbolAddress((void**)&kva,  g_kva);
    cudaGetSymbolAddress((void**)&kvcn, g_kvcn);
    cudaGetSymbolAddress((void**)&krope,g_krope);
    cudaGetSymbolAddress((void**)&kv,   g_kv);
    cudaGetSymbolAddress((void**)&kTp,  g_kT);
    cudaGetSymbolAddress((void**)&vTp,  g_vT);
    cudaGetSymbolAddress((void**)&aop,  g_ao);

    cudaFuncSetAttribute(attn_kernel, cudaFuncAttributeMaxDynamicSharedMemorySize, SMEM_ATTN);

    // Q path
    launch_gemm(x, wq_a, qa, MROWS, QLORA, DD);
    rmsnorm_kernel<<<MROWS, 256>>>(qa, q_norm_w, qa, QLORA);
    launch_gemm(qa, wq_b, q, MROWS, HH * QKD, QLORA);
    {
        dim3 g(NN, HH, BB);
        qrope_kernel<<<g, 192>>>(q, rope_cos, rope_sin, qTp);
    }

    // KV path
    launch_gemm(x, wkv_a, kva, MROWS, DROPE + KVLORA, DD);
    kva_kernel<<<MROWS, 256>>>(kva, kv_norm_w, rope_cos, rope_sin, krope, kvcn);
    launch_gemm(kvcn, wkv_b, kv, MROWS, HH * (DNOPE + DVAL), KVLORA);
    {
        dim3 g(NN, HH, BB);
        buildkv_kernel<<<g, 192>>>(kv, krope, kTp, vTp);
    }

    // attention
    {
        dim3 g(NN / 64, HH, BB);
        attn_kernel<<<g, 256, SMEM_ATTN>>>(qTp, kTp, vTp, aop);
    }

    // output projection
    launch_gemm(aop, w_out, out, MROWS, DD, HH * DVAL);
}

// round 4
// speedup vs baseline: 2.8912x; 1.6720x over previous
#include <cuda_runtime.h>
#include <cuda_bf16.h>
#include <cstdint>
#include <math.h>

// ---------------- problem constants ----------------
#define BB 2
#define NN 2048
#define DD 2048
#define HH 16
#define QLORA 1536
#define KVLORA 512
#define DNOPE 128
#define DROPE 64
#define DVAL 128
#define QKD 192            // DNOPE + DROPE
#define MROWS (BB*NN)      // 4096
#define EPS 1e-6f
#define ATTN_SCALE 0.072168783648703220563f  // 192^-0.5

// ---------------- scratch (device globals; no cudaMalloc allowed) ----------
__device__ float g_qa  [(size_t)MROWS*QLORA];
__device__ float g_q   [(size_t)MROWS*HH*QKD];
__device__ float g_qT  [(size_t)BB*HH*NN*QKD];
__device__ float g_kva [(size_t)MROWS*(DROPE+KVLORA)];
__device__ float g_kvcn[(size_t)MROWS*KVLORA];
__device__ float g_krope[(size_t)MROWS*DROPE];
__device__ float g_kv  [(size_t)MROWS*HH*(DNOPE+DVAL)];
__device__ float g_kT  [(size_t)BB*HH*NN*QKD];
__device__ float g_vT  [(size_t)BB*HH*NN*DVAL];
__device__ float g_ao  [(size_t)MROWS*HH*DVAL];

// ---------------- helpers ----------------
__device__ __forceinline__ uint32_t f2tf32(float x) {
    uint32_t r;
    asm("cvt.rna.tf32.f32 %0, %1;" : "=r"(r) : "f"(x));
    return r;
}

__device__ __forceinline__ void mma_tf32(float* c, const uint32_t* a, const uint32_t* b) {
    asm volatile(
        "mma.sync.aligned.m16n8k8.row.col.f32.tf32.tf32.f32 "
        "{%0,%1,%2,%3}, {%4,%5,%6,%7}, {%8,%9}, {%0,%1,%2,%3};"
        : "+f"(c[0]), "+f"(c[1]), "+f"(c[2]), "+f"(c[3])
        : "r"(a[0]), "r"(a[1]), "r"(a[2]), "r"(a[3]), "r"(b[0]), "r"(b[1]));
}

__device__ __forceinline__ float block_reduce_sum(float v) {
    __shared__ float red[32];
    int lane = threadIdx.x & 31, w = threadIdx.x >> 5;
    #pragma unroll
    for (int o = 16; o; o >>= 1) v += __shfl_xor_sync(0xffffffffu, v, o);
    if (lane == 0) red[w] = v;
    __syncthreads();
    int nw = blockDim.x >> 5;
    float r = (threadIdx.x < nw) ? red[threadIdx.x] : 0.f;
    if (w == 0) {
        #pragma unroll
        for (int o = 16; o; o >>= 1) r += __shfl_xor_sync(0xffffffffu, r, o);
        if (lane == 0) red[0] = r;
    }
    __syncthreads();
    float out = red[0];
    __syncthreads();
    return out;
}

// ---------------- tf32 tensor-core GEMM: C[M,N] = A[M,K] @ B[K,N] ----------
template <int BN>
__global__ __launch_bounds__(256) void gemm_tf32(
    const float* __restrict__ A, const float* __restrict__ B,
    float* __restrict__ C, int M, int N, int K) {
    constexpr int NFRAG = BN / 16;
    constexpr int BPITCH = BN + 8;
    __shared__ uint32_t As[2][16][136];
    __shared__ uint32_t Bs[2][16][BPITCH];

    const int tid = threadIdx.x;
    const int wid = tid >> 5, lane = tid & 31;
    const int g = lane >> 2, tg = lane & 3;
    const int wm = (wid & 3) * 32;
    const int wn = (wid >> 2) * (BN / 2);
    const int row0 = blockIdx.y * 128;
    const int col0 = blockIdx.x * BN;

    const int ar  = tid >> 2;
    const int akc = (tid & 3) * 4;
    const float* Ag0 = A + (size_t)(row0 + ar) * K + akc;
    const float* Ag1 = Ag0 + (size_t)64 * K;

    int brow, bcol;
    if (BN == 128) { brow = tid >> 5; bcol = (tid & 31) * 4; }
    else           { brow = tid >> 4; bcol = (tid & 15) * 4; }
    const float* Bg0 = B + (size_t)brow * N + col0 + bcol;
    const float* Bg1 = Bg0 + (size_t)8 * N;

    float acc[2][NFRAG][4];
    #pragma unroll
    for (int i = 0; i < 2; i++)
        #pragma unroll
        for (int j = 0; j < NFRAG; j++)
            #pragma unroll
            for (int k = 0; k < 4; k++) acc[i][j][k] = 0.f;

    const int ntiles = K / 16;

    {
        float4 va0 = *reinterpret_cast<const float4*>(Ag0);
        float4 va1 = *reinterpret_cast<const float4*>(Ag1);
        As[0][akc + 0][ar] = f2tf32(va0.x); As[0][akc + 1][ar] = f2tf32(va0.y);
        As[0][akc + 2][ar] = f2tf32(va0.z); As[0][akc + 3][ar] = f2tf32(va0.w);
        As[0][akc + 0][ar + 64] = f2tf32(va1.x); As[0][akc + 1][ar + 64] = f2tf32(va1.y);
        As[0][akc + 2][ar + 64] = f2tf32(va1.z); As[0][akc + 3][ar + 64] = f2tf32(va1.w);
        float4 vb0 = *reinterpret_cast<const float4*>(Bg0);
        uint4 u0 = make_uint4(f2tf32(vb0.x), f2tf32(vb0.y), f2tf32(vb0.z), f2tf32(vb0.w));
        *reinterpret_cast<uint4*>(&Bs[0][brow][bcol]) = u0;
        if (BN == 128) {
            float4 vb1 = *reinterpret_cast<const float4*>(Bg1);
            uint4 u1 = make_uint4(f2tf32(vb1.x), f2tf32(vb1.y), f2tf32(vb1.z), f2tf32(vb1.w));
            *reinterpret_cast<uint4*>(&Bs[0][brow + 8][bcol]) = u1;
        }
    }
    __syncthreads();

    for (int t = 0; t < ntiles; t++) {
        const int cur = t & 1;
        float4 na0, na1, nb0, nb1;
        const bool more = (t + 1 < ntiles);
        if (more) {
            na0 = *reinterpret_cast<const float4*>(Ag0 + (t + 1) * 16);
            na1 = *reinterpret_cast<const float4*>(Ag1 + (t + 1) * 16);
            nb0 = *reinterpret_cast<const float4*>(Bg0 + (size_t)(t + 1) * 16 * N);
            if (BN == 128)
                nb1 = *reinterpret_cast<const float4*>(Bg1 + (size_t)(t + 1) * 16 * N);
        }

        #pragma unroll
        for (int s = 0; s < 2; s++) {
            uint32_t af[2][4];
            #pragma unroll
            for (int mf = 0; mf < 2; mf++) {
                int m = wm + mf * 16 + g;
                af[mf][0] = As[cur][s * 8 + tg    ][m];
                af[mf][1] = As[cur][s * 8 + tg    ][m + 8];
                af[mf][2] = As[cur][s * 8 + tg + 4][m];
                af[mf][3] = As[cur][s * 8 + tg + 4][m + 8];
            }
            uint32_t bf[NFRAG][2];
            #pragma unroll
            for (int j = 0; j < NFRAG; j++) {
                int n = wn + j * 8 + g;
                bf[j][0] = Bs[cur][s * 8 + tg    ][n];
                bf[j][1] = Bs[cur][s * 8 + tg + 4][n];
            }
            #pragma unroll
            for (int mf = 0; mf < 2; mf++)
                #pragma unroll
                for (int j = 0; j < NFRAG; j++)
                    mma_tf32(acc[mf][j], af[mf], bf[j]);
        }

        if (more) {
            const int nxt = cur ^ 1;
            As[nxt][akc + 0][ar] = f2tf32(na0.x); As[nxt][akc + 1][ar] = f2tf32(na0.y);
            As[nxt][akc + 2][ar] = f2tf32(na0.z); As[nxt][akc + 3][ar] = f2tf32(na0.w);
            As[nxt][akc + 0][ar + 64] = f2tf32(na1.x); As[nxt][akc + 1][ar + 64] = f2tf32(na1.y);
            As[nxt][akc + 2][ar + 64] = f2tf32(na1.z); As[nxt][akc + 3][ar + 64] = f2tf32(na1.w);
            uint4 u0 = make_uint4(f2tf32(nb0.x), f2tf32(nb0.y), f2tf32(nb0.z), f2tf32(nb0.w));
            *reinterpret_cast<uint4*>(&Bs[nxt][brow][bcol]) = u0;
            if (BN == 128) {
                uint4 u1 = make_uint4(f2tf32(nb1.x), f2tf32(nb1.y), f2tf32(nb1.z), f2tf32(nb1.w));
                *reinterpret_cast<uint4*>(&Bs[nxt][brow + 8][bcol]) = u1;
            }
            __syncthreads();
        }
    }

    #pragma unroll
    for (int mf = 0; mf < 2; mf++) {
        #pragma unroll
        for (int j = 0; j < NFRAG; j++) {
            int r = row0 + wm + mf * 16 + g;
            int c = col0 + wn + j * 8 + tg * 2;
            *reinterpret_cast<float2*>(C + (size_t)r * N + c) =
                make_float2(acc[mf][j][0], acc[mf][j][1]);
            *reinterpret_cast<float2*>(C + (size_t)(r + 8) * N + c) =
                make_float2(acc[mf][j][2], acc[mf][j][3]);
        }
    }
}

// ---------------- rmsnorm over rows ----------------
__global__ __launch_bounds__(256) void rmsnorm_kernel(
    const float* __restrict__ in, const float* __restrict__ w,
    float* __restrict__ out, int W) {
    size_t row = blockIdx.x;
    const float* r = in + row * W;
    float ss = 0.f;
    for (int i = threadIdx.x; i < W; i += 256) { float v = r[i]; ss += v * v; }
    ss = block_reduce_sum(ss);
    float sc = rsqrtf(ss / (float)W + EPS);
    for (int i = threadIdx.x; i < W; i += 256)
        out[row * W + i] = r[i] * sc * w[i];
}

// ---------------- q rope + transpose to [b,h,n,192] ------------------------
__global__ __launch_bounds__(192) void qrope_kernel(
    const float* __restrict__ q, const float* __restrict__ cosv,
    const float* __restrict__ sinv, float* __restrict__ qT) {
    int n = blockIdx.x, h = blockIdx.y, b = blockIdx.z;
    int d = threadIdx.x;
    const float* src = q + ((size_t)(b * NN + n) * HH + h) * QKD;
    float v;
    if (d < DNOPE) {
        v = src[d];
    } else {
        int r = d - DNOPE;
        int i = r >> 1;
        float x0 = src[DNOPE + 2 * i], x1 = src[DNOPE + 2 * i + 1];
        float c = cosv[n * (DROPE / 2) + i], s = sinv[n * (DROPE / 2) + i];
        v = (r & 1) ? fmaf(x0, s, x1 * c) : fmaf(x0, c, -x1 * s);
    }
    qT[(((size_t)b * HH + h) * NN + n) * QKD + d] = v;
}

// ---------------- kv_a: rope(k_rope) + rmsnorm(kv_c) ------------------------
__global__ __launch_bounds__(256) void kva_kernel(
    const float* __restrict__ kva, const float* __restrict__ kvw,
    const float* __restrict__ cosv, const float* __restrict__ sinv,
    float* __restrict__ krope, float* __restrict__ kvcn) {
    size_t row = blockIdx.x;
    int n = (int)(row % NN);
    const float* src = kva + row * (DROPE + KVLORA);
    float ss = 0.f;
    for (int i = threadIdx.x; i < KVLORA; i += 256) {
        float v = src[DROPE + i]; ss += v * v;
    }
    ss = block_reduce_sum(ss);
    float sc = rsqrtf(ss / (float)KVLORA + EPS);
    for (int i = threadIdx.x; i < KVLORA; i += 256)
        kvcn[row * KVLORA + i] = src[DROPE + i] * sc * kvw[i];
    if (threadIdx.x < DROPE) {
        int t = threadIdx.x;
        int i = t >> 1;
        float x0 = src[2 * i], x1 = src[2 * i + 1];
        float c = cosv[n * (DROPE / 2) + i], s = sinv[n * (DROPE / 2) + i];
        krope[row * DROPE + t] = (t & 1) ? fmaf(x0, s, x1 * c) : fmaf(x0, c, -x1 * s);
    }
}

// ---------------- build K [b,h,n,192] and V [b,h,n,128] ---------------------
__global__ __launch_bounds__(192) void buildkv_kernel(
    const float* __restrict__ kv, const float* __restrict__ krope,
    float* __restrict__ kT, float* __restrict__ vT) {
    int n = blockIdx.x, h = blockIdx.y, b = blockIdx.z;
    int d = threadIdx.x;
    size_t row = (size_t)b * NN + n;
    const float* src = kv + (row * HH + h) * (DNOPE + DVAL);
    size_t o = ((size_t)b * HH + h) * NN + n;
    if (d < DNOPE) {
        kT[o * QKD + d] = src[d];
        vT[o * DVAL + d] = src[DNOPE + d];
    } else {
        kT[o * QKD + d] = krope[row * DROPE + (d - DNOPE)];
    }
}

// ---------------- flash attention (causal), tf32 MMA, BQ=128, BK=64 --------
// 8 warps; warp w owns Q rows [w*16, w*16+16). Per warp:
//   S(16x64) = Q(16x192) @ K^T : 24 k-steps x 8 n-frags of m16n8k8
//   softmax in C-frag layout (shfl over tg group)
//   P staged to warp-private smem rows -> A-frags for O(16x128) += P @ V
// smem pitches give conflict-free fragment reads:
//   Q/K pitch 196 (bank=4g+tg), V pitch 136 (bank=8tg+g), P pitch 68.
#define AQP 196
#define AKP 196
#define AVP 136
#define APP 68
#define SMEM_ATTN ((128*AQP + 64*AKP + 64*AVP + 128*APP) * 4)

__global__ __launch_bounds__(256, 1) void attn_tf32(
    const float* __restrict__ qT, const float* __restrict__ kT,
    const float* __restrict__ vT, float* __restrict__ ao) {
    extern __shared__ uint32_t smu[];
    uint32_t* Qs = smu;                    // [128][196]
    uint32_t* Ks = Qs + 128 * AQP;         // [64][196]
    uint32_t* Vs = Ks + 64 * AKP;          // [64][136]
    uint32_t* Ps = Vs + 64 * AVP;          // [128][68]

    const int tid = threadIdx.x;
    const int wid = tid >> 5, lane = tid & 31;
    const int g = lane >> 2, tg = lane & 3;
    const int wm = wid * 16;
    const int qt = blockIdx.x, h = blockIdx.y, b = blockIdx.z;
    const int q0 = qt * 128;
    const size_t bh = ((size_t)b * HH + h) * NN;

    // ---- load Q tile (128 x 192) as tf32 ----
    const float* Qg = qT + (bh + q0) * QKD;
    for (int i = tid; i < 128 * 48; i += 256) {
        int r = i / 48, c4 = (i % 48) * 4;
        float4 v = *reinterpret_cast<const float4*>(Qg + (size_t)r * QKD + c4);
        uint4 u = make_uint4(f2tf32(v.x), f2tf32(v.y), f2tf32(v.z), f2tf32(v.w));
        *reinterpret_cast<uint4*>(&Qs[r * AQP + c4]) = u;
    }

    float oacc[16][4];
    #pragma unroll
    for (int j = 0; j < 16; j++)
        #pragma unroll
        for (int c = 0; c < 4; c++) oacc[j][c] = 0.f;
    float m0 = -1e30f, m1 = -1e30f, l0 = 0.f, l1 = 0.f;

    const int row0 = q0 + wm + g;
    const int row1 = row0 + 8;
    const int nkt = q0 / 64 + 2;

    for (int kt = 0; kt < nkt; kt++) {
        __syncthreads();   // protect Ks/Vs from prior-iteration readers (and Qs first time)
        const float* Kg = kT + (bh + (size_t)kt * 64) * QKD;
        const float* Vg = vT + (bh + (size_t)kt * 64) * DVAL;
        for (int i = tid; i < 64 * 48; i += 256) {
            int r = i / 48, c4 = (i % 48) * 4;
            float4 v = *reinterpret_cast<const float4*>(Kg + (size_t)r * QKD + c4);
            uint4 u = make_uint4(f2tf32(v.x), f2tf32(v.y), f2tf32(v.z), f2tf32(v.w));
            *reinterpret_cast<uint4*>(&Ks[r * AKP + c4]) = u;
        }
        for (int i = tid; i < 64 * 32; i += 256) {
            int r = i / 32, c4 = (i % 32) * 4;
            float4 v = *reinterpret_cast<const float4*>(Vg + (size_t)r * DVAL + c4);
            uint4 u = make_uint4(f2tf32(v.x), f2tf32(v.y), f2tf32(v.z), f2tf32(v.w));
            *reinterpret_cast<uint4*>(&Vs[r * AVP + c4]) = u;
        }
        __syncthreads();

        // ---- S = Q K^T ----
        float sacc[8][4];
        #pragma unroll
        for (int j = 0; j < 8; j++)
            #pragma unroll
            for (int c = 0; c < 4; c++) sacc[j][c] = 0.f;

        #pragma unroll 4
        for (int s = 0; s < 24; s++) {
            uint32_t af[4];
            af[0] = Qs[(wm + g) * AQP + s * 8 + tg];
            af[1] = Qs[(wm + g + 8) * AQP + s * 8 + tg];
            af[2] = Qs[(wm + g) * AQP + s * 8 + tg + 4];
            af[3] = Qs[(wm + g + 8) * AQP + s * 8 + tg + 4];
            #pragma unroll
            for (int j = 0; j < 8; j++) {
                uint32_t bf[2];
                bf[0] = Ks[(j * 8 + g) * AKP + s * 8 + tg];
                bf[1] = Ks[(j * 8 + g) * AKP + s * 8 + tg + 4];
                mma_tf32(sacc[j], af, bf);
            }
        }

        // ---- scale + causal mask ----
        const bool masked = (kt >= 2 * qt);
        #pragma unroll
        for (int j = 0; j < 8; j++) {
            #pragma unroll
            for (int c = 0; c < 4; c++) sacc[j][c] *= ATTN_SCALE;
            if (masked) {
                int col = kt * 64 + j * 8 + 2 * tg;
                if (col     > row0) sacc[j][0] = -1e30f;
                if (col + 1 > row0) sacc[j][1] = -1e30f;
                if (col     > row1) sacc[j][2] = -1e30f;
                if (col + 1 > row1) sacc[j][3] = -1e30f;
            }
        }

        // ---- online softmax (per-row reductions over tg group) ----
        float mx0 = -1e30f, mx1 = -1e30f;
        #pragma unroll
        for (int j = 0; j < 8; j++) {
            mx0 = fmaxf(mx0, fmaxf(sacc[j][0], sacc[j][1]));
            mx1 = fmaxf(mx1, fmaxf(sacc[j][2], sacc[j][3]));
        }
        mx0 = fmaxf(mx0, __shfl_xor_sync(0xffffffffu, mx0, 1));
        mx0 = fmaxf(mx0, __shfl_xor_sync(0xffffffffu, mx0, 2));
        mx1 = fmaxf(mx1, __shfl_xor_sync(0xffffffffu, mx1, 1));
        mx1 = fmaxf(mx1, __shfl_xor_sync(0xffffffffu, mx1, 2));

        float mn0 = fmaxf(m0, mx0), mn1 = fmaxf(m1, mx1);
        float a0 = __expf(m0 - mn0), a1 = __expf(m1 - mn1);
        float ps0 = 0.f, ps1 = 0.f;
        #pragma unroll
        for (int j = 0; j < 8; j++) {
            float p00 = __expf(sacc[j][0] - mn0);
            float p01 = __expf(sacc[j][1] - mn0);
            float p10 = __expf(sacc[j][2] - mn1);
            float p11 = __expf(sacc[j][3] - mn1);
            ps0 += p00 + p01; ps1 += p10 + p11;
            int cc = j * 8 + 2 * tg;
            Ps[(wm + g) * APP + cc]     = f2tf32(p00);
            Ps[(wm + g) * APP + cc + 1] = f2tf32(p01);
            Ps[(wm + g + 8) * APP + cc]     = f2tf32(p10);
            Ps[(wm + g + 8) * APP + cc + 1] = f2tf32(p11);
        }
        ps0 += __shfl_xor_sync(0xffffffffu, ps0, 1);
        ps0 += __shfl_xor_sync(0xffffffffu, ps0, 2);
        ps1 += __shfl_xor_sync(0xffffffffu, ps1, 1);
        ps1 += __shfl_xor_sync(0xffffffffu, ps1, 2);

        l0 = l0 * a0 + ps0; m0 = mn0;
        l1 = l1 * a1 + ps1; m1 = mn1;
        #pragma unroll
        for (int j = 0; j < 16; j++) {
            oacc[j][0] *= a0; oacc[j][1] *= a0;
            oacc[j][2] *= a1; oacc[j][3] *= a1;
        }

        __syncwarp();  // Ps region is warp-private: warp-level visibility suffices

        // ---- O += P V ----
        #pragma unroll
        for (int s = 0; s < 8; s++) {
            uint32_t af[4];
            af[0] = Ps[(wm + g) * APP + s * 8 + tg];
            af[1] = Ps[(wm + g + 8) * APP + s * 8 + tg];
            af[2] = Ps[(wm + g) * APP + s * 8 + tg + 4];
            af[3] = Ps[(wm + g + 8) * APP + s * 8 + tg + 4];
            #pragma unroll
            for (int j = 0; j < 16; j++) {
                uint32_t bf[2];
                bf[0] = Vs[(s * 8 + tg) * AVP + j * 8 + g];
                bf[1] = Vs[(s * 8 + tg + 4) * AVP + j * 8 + g];
                mma_tf32(oacc[j], af, bf);
            }
        }
        __syncwarp();  // keep Ps writes of next iter ordered after these reads
    }

    // ---- epilogue ----
    float inv0 = 1.f / l0, inv1 = 1.f / l1;
    #pragma unroll
    for (int j = 0; j < 16; j++) {
        int col = h * DVAL + j * 8 + 2 * tg;
        *reinterpret_cast<float2*>(ao + ((size_t)b * NN + row0) * (HH * DVAL) + col) =
            make_float2(oacc[j][0] * inv0, oacc[j][1] * inv0);
        *reinterpret_cast<float2*>(ao + ((size_t)b * NN + row1) * (HH * DVAL) + col) =
            make_float2(oacc[j][2] * inv1, oacc[j][3] * inv1);
    }
}

// ---------------- launch -----------------------------------------------------
static void launch_gemm(const float* A, const float* B, float* C, int M, int N, int K) {
    if (N % 128 == 0) {
        dim3 grid(N / 128, M / 128);
        gemm_tf32<128><<<grid, 256>>>(A, B, C, M, N, K);
    } else {
        dim3 grid(N / 64, M / 128);
        gemm_tf32<64><<<grid, 256>>>(A, B, C, M, N, K);
    }
}

extern "C" void kernel_launch(void* const* d_in, const int* in_sizes, int n_in,
                              void* d_out, int out_size) {
    const float* x        = (const float*)d_in[0];
    const float* rope_cos = (const float*)d_in[2];
    const float* rope_sin = (const float*)d_in[3];
    const float* wq_a     = (const float*)d_in[4];
    const float* q_norm_w = (const float*)d_in[5];
    const float* wq_b     = (const float*)d_in[6];
    const float* wkv_a    = (const float*)d_in[7];
    const float* kv_norm_w= (const float*)d_in[8];
    const float* wkv_b    = (const float*)d_in[9];
    const float* w_out    = (const float*)d_in[10];
    float* out = (float*)d_out;

    float *qa, *q, *qTp, *kva, *kvcn, *krope, *kv, *kTp, *vTp, *aop;
    cudaGetSymbolAddress((void**)&qa,   g_qa);
    cudaGetSymbolAddress((void**)&q,    g_q);
    cudaGetSymbolAddress((void**)&qTp,  g_qT);
    cudaGetSymbolAddress((void**)&kva,  g_kva);
    cudaGetSymbolAddress((void**)&kvcn, g_kvcn);
    cudaGetSymbolAddress((void**)&krope,g_krope);
    cudaGetSymbolAddress((void**)&kv,   g_kv);
    cudaGetSymbolAddress((void**)&kTp,  g_kT);
    cudaGetSymbolAddress((void**)&vTp,  g_vT);
    cudaGetSymbolAddress((void**)&aop,  g_ao);

    cudaFuncSetAttribute(attn_tf32, cudaFuncAttributeMaxDynamicSharedMemorySize, SMEM_ATTN);

    // Q path
    launch_gemm(x, wq_a, qa, MROWS, QLORA, DD);
    rmsnorm_kernel<<<MROWS, 256>>>(qa, q_norm_w, qa, QLORA);
    launch_gemm(qa, wq_b, q, MROWS, HH * QKD, QLORA);
    {
        dim3 g(NN, HH, BB);
        qrope_kernel<<<g, 192>>>(q, rope_cos, rope_sin, qTp);
    }

    // KV path
    launch_gemm(x, wkv_a, kva, MROWS, DROPE + KVLORA, DD);
    kva_kernel<<<MROWS, 256>>>(kva, kv_norm_w, rope_cos, rope_sin, krope, kvcn);
    launch_gemm(kvcn, wkv_b, kv, MROWS, HH * (DNOPE + DVAL), KVLORA);
    {
        dim3 g(NN, HH, BB);
        buildkv_kernel<<<g, 192>>>(kv, krope, kTp, vTp);
    }

    // attention (tf32 MMA)
    {
        dim3 g(NN / 128, HH, BB);
        attn_tf32<<<g, 256, SMEM_ATTN>>>(qTp, kTp, vTp, aop);
    }

    // output projection
    launch_gemm(aop, w_out, out, MROWS, DD, HH * DVAL);
}